// round 1
// baseline (speedup 1.0000x reference)
#include <cuda_runtime.h>

#define NN_MAX 50000
#define NE_MAX 800000
#define EIN_LD 132   // padded row stride (floats) for 128-wide smem tiles

// ---------------- device scratch (no allocations allowed) ----------------
__device__ float g_flow_in[NN_MAX * 64];
__device__ float g_flow_out[NN_MAX * 64];
__device__ int   g_out_list[NE_MAX];
__device__ int   g_in_list[NE_MAX];
__device__ int   g_counts[2];   // [0]=out (row<col), [1]=in (row>col)
__device__ int   g_is64;        // 1 if edge_index is int64, 0 if int32

// ---------------- init: zero accumulators, counters, detect index dtype ----
__global__ void init_kernel(const void* eidx, int nN) {
    int i = blockIdx.x * blockDim.x + threadIdx.x;
    float4 z = make_float4(0.f, 0.f, 0.f, 0.f);
    int total = nN * 16;  // nN*64 floats / 4
    if (i < total) {
        ((float4*)g_flow_in)[i]  = z;
        ((float4*)g_flow_out)[i] = z;
    }
    if (i == 0) {
        g_counts[0] = 0;
        g_counts[1] = 0;
        // int64 values < 2^31 -> every odd 32-bit word is 0.
        // int32 random values in [0,50000) -> essentially surely some odd word nonzero.
        const int* w = (const int*)eidx;
        int nz = 0;
        #pragma unroll
        for (int k = 0; k < 32; k++) nz |= w[2 * k + 1];
        g_is64 = (nz == 0) ? 1 : 0;
    }
}

// ---------------- compaction: split edges by direction (warp-aggregated) ----
__global__ void compact_kernel(const void* eidx, int nE) {
    int e = blockIdx.x * blockDim.x + threadIdx.x;
    int lane = threadIdx.x & 31;
    bool is_out = false, is_in = false;
    if (e < nE) {
        int r, c;
        if (g_is64) {
            const long long* p = (const long long*)eidx;
            r = (int)p[e];
            c = (int)p[nE + e];
        } else {
            const int* p = (const int*)eidx;
            r = p[e];
            c = p[nE + e];
        }
        is_out = (r < c);
        is_in  = (r > c);
    }
    unsigned mo = __ballot_sync(0xffffffffu, is_out);
    unsigned mi = __ballot_sync(0xffffffffu, is_in);
    int bo = 0, bi = 0;
    if (lane == 0) {
        if (mo) bo = atomicAdd(&g_counts[0], __popc(mo));
        if (mi) bi = atomicAdd(&g_counts[1], __popc(mi));
    }
    bo = __shfl_sync(0xffffffffu, bo, 0);
    bi = __shfl_sync(0xffffffffu, bi, 0);
    unsigned lt = (1u << lane) - 1u;
    if (is_out) g_out_list[bo + __popc(mo & lt)] = e;
    if (is_in)  g_in_list [bi + __popc(mi & lt)] = e;
}

// ---------------- fused 2-layer MLP over 64-row chunks ----------------
// which==0: edges in g_out_list -> atomic scatter into g_flow_out[row]
// which==1: edges in g_in_list  -> atomic scatter into g_flow_in[row]
// which==2: nodes; input = concat(flow_in, flow_out); direct store to out
//
// Input row (128 f32) = concat(A[aIdx]*64.., B[bIdx]*64..)
// Layer1: 128->128 relu, Layer2: 128->64 relu.
__global__ void __launch_bounds__(256, 1) mlp_kernel(
    int which, int nN, int nE,
    const float* __restrict__ x, const void* __restrict__ eidx,
    const float* __restrict__ eattr,
    const float* __restrict__ W1, const float* __restrict__ b1,
    const float* __restrict__ W2, const float* __restrict__ b2,
    float* __restrict__ nodeout)
{
    extern __shared__ float smem[];
    float* sW1 = smem;                    // 128*128
    float* sW2 = sW1 + 128 * 128;         // 128*64
    float* sb1 = sW2 + 128 * 64;          // 128
    float* sb2 = sb1 + 128;               // 64
    float* sIn = sb2 + 64;                // 64*EIN_LD
    float* sH1 = sIn + 64 * EIN_LD;       // 64*EIN_LD
    int*   sIdx = (int*)(sH1 + 64 * EIN_LD);  // 64

    const int tid = threadIdx.x;

    // stage weights/biases once per block
    for (int i = tid; i < (128 * 128) / 4; i += 256)
        ((float4*)sW1)[i] = ((const float4*)W1)[i];
    for (int i = tid; i < (128 * 64) / 4; i += 256)
        ((float4*)sW2)[i] = ((const float4*)W2)[i];
    if (tid < 128) sb1[tid] = b1[tid];
    if (tid < 64)  sb2[tid] = b2[tid];

    int count;
    const int* list = nullptr;
    float* scatp = nullptr;
    const float* Aptr;
    const float* Bptr;
    if (which == 0) { count = g_counts[0]; list = g_out_list; scatp = g_flow_out; Aptr = x; Bptr = eattr; }
    else if (which == 1) { count = g_counts[1]; list = g_in_list; scatp = g_flow_in; Aptr = x; Bptr = eattr; }
    else { count = nN; Aptr = g_flow_in; Bptr = g_flow_out; }

    const int is64 = g_is64;
    const long long* p64 = (const long long*)eidx;
    const int* p32 = (const int*)eidx;

    __syncthreads();

    const int r = tid >> 4;   // 0..15  (edge/row group)
    const int c = tid & 15;   // 0..15  (column group)

    int nch = (count + 63) >> 6;
    for (int ch = blockIdx.x; ch < nch; ch += gridDim.x) {
        int base = ch << 6;

        // ---- gather input tile: 4 threads per row, 32 floats each ----
        {
            int slot = tid >> 2;
            int part = tid & 3;
            int idx = base + slot;
            bool valid = idx < count;
            long long aIdx = 0, bIdx = 0;
            int scat = -1;
            if (valid) {
                if (which < 2) {
                    int eid = list[idx];
                    int rr, cc;
                    if (is64) { rr = (int)p64[eid]; cc = (int)p64[nE + eid]; }
                    else      { rr = p32[eid];      cc = p32[nE + eid]; }
                    scat = rr; aIdx = cc; bIdx = eid;
                } else {
                    scat = idx; aIdx = idx; bIdx = idx;
                }
            }
            if (part == 0) sIdx[slot] = scat;
            float4* dst = (float4*)&sIn[slot * EIN_LD] + part * 8;
            if (valid) {
                const float4* src = (part < 2)
                    ? ((const float4*)(Aptr + aIdx * 64) + part * 8)
                    : ((const float4*)(Bptr + bIdx * 64) + (part - 2) * 8);
                #pragma unroll
                for (int i = 0; i < 8; i++) dst[i] = src[i];
            } else {
                float4 z = make_float4(0.f, 0.f, 0.f, 0.f);
                #pragma unroll
                for (int i = 0; i < 8; i++) dst[i] = z;
            }
        }
        __syncthreads();

        // ---- GEMM1: sH1[64,128] = relu(sIn[64,128] @ sW1[128,128] + b1) ----
        {
            float acc[4][8];
            #pragma unroll
            for (int j = 0; j < 8; j++) {
                float bv = sb1[(j >> 2) * 64 + 4 * c + (j & 3)];
                #pragma unroll
                for (int ii = 0; ii < 4; ii++) acc[ii][j] = bv;
            }
            #pragma unroll 4
            for (int k = 0; k < 128; k++) {
                float a0 = sIn[(r +  0) * EIN_LD + k];
                float a1 = sIn[(r + 16) * EIN_LD + k];
                float a2 = sIn[(r + 32) * EIN_LD + k];
                float a3 = sIn[(r + 48) * EIN_LD + k];
                float4 w0 = *(const float4*)&sW1[k * 128 + 4 * c];
                float4 w1 = *(const float4*)&sW1[k * 128 + 64 + 4 * c];
                float wv[8] = {w0.x, w0.y, w0.z, w0.w, w1.x, w1.y, w1.z, w1.w};
                float av[4] = {a0, a1, a2, a3};
                #pragma unroll
                for (int ii = 0; ii < 4; ii++)
                    #pragma unroll
                    for (int j = 0; j < 8; j++)
                        acc[ii][j] = fmaf(av[ii], wv[j], acc[ii][j]);
            }
            #pragma unroll
            for (int ii = 0; ii < 4; ii++) {
                int e = r + 16 * ii;
                #pragma unroll
                for (int q = 0; q < 2; q++) {
                    float4 v;
                    v.x = fmaxf(acc[ii][q * 4 + 0], 0.f);
                    v.y = fmaxf(acc[ii][q * 4 + 1], 0.f);
                    v.z = fmaxf(acc[ii][q * 4 + 2], 0.f);
                    v.w = fmaxf(acc[ii][q * 4 + 3], 0.f);
                    *(float4*)&sH1[e * EIN_LD + q * 64 + 4 * c] = v;
                }
            }
        }
        __syncthreads();

        // ---- GEMM2 + relu + scatter: out[64,64] = relu(sH1 @ sW2 + b2) ----
        {
            float acc[4][4];
            #pragma unroll
            for (int m = 0; m < 4; m++) {
                float bv = sb2[4 * c + m];
                #pragma unroll
                for (int ii = 0; ii < 4; ii++) acc[ii][m] = bv;
            }
            #pragma unroll 8
            for (int k = 0; k < 128; k++) {
                float a0 = sH1[(r +  0) * EIN_LD + k];
                float a1 = sH1[(r + 16) * EIN_LD + k];
                float a2 = sH1[(r + 32) * EIN_LD + k];
                float a3 = sH1[(r + 48) * EIN_LD + k];
                float4 w = *(const float4*)&sW2[k * 64 + 4 * c];
                float av[4] = {a0, a1, a2, a3};
                #pragma unroll
                for (int ii = 0; ii < 4; ii++) {
                    acc[ii][0] = fmaf(av[ii], w.x, acc[ii][0]);
                    acc[ii][1] = fmaf(av[ii], w.y, acc[ii][1]);
                    acc[ii][2] = fmaf(av[ii], w.z, acc[ii][2]);
                    acc[ii][3] = fmaf(av[ii], w.w, acc[ii][3]);
                }
            }
            #pragma unroll
            for (int ii = 0; ii < 4; ii++) {
                int node = sIdx[r + 16 * ii];
                if (node >= 0) {
                    float v0 = fmaxf(acc[ii][0], 0.f);
                    float v1 = fmaxf(acc[ii][1], 0.f);
                    float v2 = fmaxf(acc[ii][2], 0.f);
                    float v3 = fmaxf(acc[ii][3], 0.f);
                    if (which < 2) {
                        float* d = scatp + (long long)node * 64 + 4 * c;
                        atomicAdd(d + 0, v0);
                        atomicAdd(d + 1, v1);
                        atomicAdd(d + 2, v2);
                        atomicAdd(d + 3, v3);
                    } else {
                        *(float4*)(nodeout + (long long)node * 64 + 4 * c) =
                            make_float4(v0, v1, v2, v3);
                    }
                }
            }
        }
        __syncthreads();
    }
}

// ---------------- launch ----------------
extern "C" void kernel_launch(void* const* d_in, const int* in_sizes, int n_in,
                              void* d_out, int out_size) {
    const float* x     = (const float*)d_in[0];
    const void*  eidx  = d_in[1];
    const float* eattr = (const float*)d_in[2];
    const float* Wo1 = (const float*)d_in[3];
    const float* bo1 = (const float*)d_in[4];
    const float* Wo2 = (const float*)d_in[5];
    const float* bo2 = (const float*)d_in[6];
    const float* Wi1 = (const float*)d_in[7];
    const float* bi1 = (const float*)d_in[8];
    const float* Wi2 = (const float*)d_in[9];
    const float* bi2 = (const float*)d_in[10];
    const float* Wn1 = (const float*)d_in[11];
    const float* bn1 = (const float*)d_in[12];
    const float* Wn2 = (const float*)d_in[13];
    const float* bn2 = (const float*)d_in[14];

    int nN = in_sizes[0] / 64;
    int nE = in_sizes[2] / 64;

    const int SMEM_BYTES = (128 * 128 + 128 * 64 + 128 + 64 + 2 * 64 * EIN_LD) * 4 + 64 * 4;
    cudaFuncSetAttribute(mlp_kernel, cudaFuncAttributeMaxDynamicSharedMemorySize, SMEM_BYTES);

    int initBlocks = (nN * 16 + 255) / 256;
    init_kernel<<<initBlocks, 256>>>(eidx, nN);
    compact_kernel<<<(nE + 255) / 256, 256>>>(eidx, nE);

    // flow_out: edges with row<col
    mlp_kernel<<<148, 256, SMEM_BYTES>>>(0, nN, nE, x, eidx, eattr,
                                         Wo1, bo1, Wo2, bo2, nullptr);
    // flow_in: edges with row>col
    mlp_kernel<<<148, 256, SMEM_BYTES>>>(1, nN, nE, x, eidx, eattr,
                                         Wi1, bi1, Wi2, bi2, nullptr);
    // node MLP over concat(flow_in, flow_out)
    mlp_kernel<<<148, 256, SMEM_BYTES>>>(2, nN, nE, x, eidx, eattr,
                                         Wn1, bn1, Wn2, bn2, (float*)d_out);
}

// round 5
// speedup vs baseline: 2.5179x; 2.5179x over previous
#include <cuda_runtime.h>
#include <cuda_fp16.h>
#include <stdint.h>

#define NN_MAX 50000
#define NE_MAX 800000

// ---------------- device scratch ----------------
__device__ float g_flow_in[NN_MAX * 64];
__device__ float g_flow_out[NN_MAX * 64];
__device__ int   g_out_list[NE_MAX];
__device__ int   g_in_list[NE_MAX];
__device__ int   g_counts[2];   // [0]=out (row<col), [1]=in (row>col)
__device__ int   g_is64;

// ---------------- smem layout (bytes) ----------------
// rows of 128 halfs = 256B, XOR-swizzled within row
#define OFF_W1H 0         // 128n x 128k fp16   32KB
#define OFF_W1L 32768     //                    32KB
#define OFF_W2H 65536     // 64n x 128k fp16    16KB
#define OFF_W2L 81920     //                    16KB
#define OFF_A   98304     // 128m x 128k fp16   32KB
#define OFF_H1  131072    // 128m x 128k fp16   32KB
#define OFF_STG 163840    // 128 x 68 f32       34816B
#define OFF_B1  198656    // 128 f32
#define OFF_B2  199168    // 64 f32
#define OFF_IDX 199424    // 128 int
#define SMEM_TOTAL 199936

// swizzle: byte offset within tile for (row, colbyte)
#define SWZ(row, cb) ((uint32_t)(row) * 256u + (((uint32_t)(cb)) ^ ((((uint32_t)(row)) & 7u) << 4)))

__device__ __forceinline__ uint32_t smem_u32(const void* p) {
    uint32_t a;
    asm("{ .reg .u64 t; cvta.to.shared.u64 t, %1; cvt.u32.u64 %0, t; }" : "=r"(a) : "l"(p));
    return a;
}

#define LDMX4(r, a) \
    asm volatile("ldmatrix.sync.aligned.m8n8.x4.shared.b16 {%0,%1,%2,%3}, [%4];" \
        : "=r"((r)[0]), "=r"((r)[1]), "=r"((r)[2]), "=r"((r)[3]) : "r"(a))
#define LDMX2(r, a) \
    asm volatile("ldmatrix.sync.aligned.m8n8.x2.shared.b16 {%0,%1}, [%2];" \
        : "=r"((r)[0]), "=r"((r)[1]) : "r"(a))
#define MMA16816(c, a, b) \
    asm volatile("mma.sync.aligned.m16n8k16.row.col.f32.f16.f16.f32 " \
        "{%0,%1,%2,%3}, {%4,%5,%6,%7}, {%8,%9}, {%0,%1,%2,%3};" \
        : "+f"((c)[0]), "+f"((c)[1]), "+f"((c)[2]), "+f"((c)[3]) \
        : "r"((a)[0]), "r"((a)[1]), "r"((a)[2]), "r"((a)[3]), "r"((b)[0]), "r"((b)[1]))

// ---------------- init ----------------
__global__ void init_kernel(const void* eidx, int nN) {
    int i = blockIdx.x * blockDim.x + threadIdx.x;
    float4 z = make_float4(0.f, 0.f, 0.f, 0.f);
    int total = nN * 16;
    if (i < total) {
        ((float4*)g_flow_in)[i]  = z;
        ((float4*)g_flow_out)[i] = z;
    }
    if (i == 0) {
        g_counts[0] = 0;
        g_counts[1] = 0;
        const int* w = (const int*)eidx;
        int nz = 0;
        #pragma unroll
        for (int k = 0; k < 32; k++) nz |= w[2 * k + 1];
        g_is64 = (nz == 0) ? 1 : 0;
    }
}

// ---------------- compaction ----------------
__global__ void compact_kernel(const void* eidx, int nE) {
    int e = blockIdx.x * blockDim.x + threadIdx.x;
    int lane = threadIdx.x & 31;
    bool is_out = false, is_in = false;
    if (e < nE) {
        int r, c;
        if (g_is64) {
            const long long* p = (const long long*)eidx;
            r = (int)p[e]; c = (int)p[nE + e];
        } else {
            const int* p = (const int*)eidx;
            r = p[e]; c = p[nE + e];
        }
        is_out = (r < c);
        is_in  = (r > c);
    }
    unsigned mo = __ballot_sync(0xffffffffu, is_out);
    unsigned mi = __ballot_sync(0xffffffffu, is_in);
    int bo = 0, bi = 0;
    if (lane == 0) {
        if (mo) bo = atomicAdd(&g_counts[0], __popc(mo));
        if (mi) bi = atomicAdd(&g_counts[1], __popc(mi));
    }
    bo = __shfl_sync(0xffffffffu, bo, 0);
    bi = __shfl_sync(0xffffffffu, bi, 0);
    unsigned lt = (1u << lane) - 1u;
    if (is_out) g_out_list[bo + __popc(mo & lt)] = e;
    if (is_in)  g_in_list [bi + __popc(mi & lt)] = e;
}

// ---------------- fused 2-layer MLP on mma.sync tensor cores ----------------
// which==0: edges (out list) -> atomic scatter g_flow_out[row]
// which==1: edges (in list)  -> atomic scatter g_flow_in[row]
// which==2: nodes, input = concat(flow_in, flow_out) -> store nodeout
__global__ void __launch_bounds__(256, 1)
mlp_tc_kernel(int which, int nN, int nE,
              const float* __restrict__ x, const void* __restrict__ eidx,
              const float* __restrict__ eattr,
              const float* __restrict__ W1, const float* __restrict__ b1,
              const float* __restrict__ W2, const float* __restrict__ b2,
              float* __restrict__ nodeout)
{
    extern __shared__ __align__(256) char smem[];
    char* S = smem;
    const uint32_t sb = smem_u32(smem);
    const int tid = threadIdx.x;
    const int wid = tid >> 5;
    const int l = tid & 31;

    // ---- stage weights: W^T hi/lo fp16, swizzled [n][k] ----
    for (int i = tid; i < 128 * 128; i += 256) {
        int n = i >> 7, k = i & 127;
        float w = W1[k * 128 + n];
        __half hi = __float2half_rn(w);
        __half lo = __float2half_rn(w - __half2float(hi));
        uint32_t off = SWZ(n, k * 2);
        *(__half*)(S + OFF_W1H + off) = hi;
        *(__half*)(S + OFF_W1L + off) = lo;
    }
    for (int i = tid; i < 64 * 128; i += 256) {
        int n = i >> 7, k = i & 127;
        float w = W2[k * 64 + n];
        __half hi = __float2half_rn(w);
        __half lo = __float2half_rn(w - __half2float(hi));
        uint32_t off = SWZ(n, k * 2);
        *(__half*)(S + OFF_W2H + off) = hi;
        *(__half*)(S + OFF_W2L + off) = lo;
    }
    if (tid < 128) ((float*)(S + OFF_B1))[tid] = b1[tid];
    if (tid < 64)  ((float*)(S + OFF_B2))[tid] = b2[tid];

    // ---- mode setup ----
    int count;
    const int* list = nullptr;
    float* scatp = nullptr;
    const float* Ap = nullptr;
    const float* Bp = nullptr;
    if (which == 0)      { count = g_counts[0]; list = g_out_list; scatp = g_flow_out; }
    else if (which == 1) { count = g_counts[1]; list = g_in_list;  scatp = g_flow_in;  }
    else                 { count = nN; Ap = g_flow_in; Bp = g_flow_out; }
    const int is64 = g_is64;
    const long long* p64 = (const long long*)eidx;
    const int* p32 = (const int*)eidx;

    __syncthreads();

    // ---- per-lane constants ----
    const int mg = wid & 3;          // m-group: rows mg*32 .. +31
    const int nh = wid >> 2;         // n-half
    const int mbase = mg * 32;
    const int ccol = (l & 3) * 2;    // fragment column pair offset

    // A/H1 ldmatrix per-lane address pieces
    const uint32_t a_row  = (uint32_t)(mbase + (l & 15));
    const uint32_t a_cb16 = (uint32_t)((l >> 4) * 16);
    const uint32_t a_xor  = (a_row & 7u) << 4;
    const uint32_t aA  = sb + OFF_A  + a_row * 256u;
    const uint32_t aH  = sb + OFF_H1 + a_row * 256u;

    // B ldmatrix per-lane address pieces (lanes 0-15 meaningful; others replicate)
    const uint32_t bl    = (uint32_t)(l & 15);
    const uint32_t b_cb16 = ((bl >> 3) & 1u) * 16u;
    const uint32_t b_xor  = (bl & 7u) << 4;
    const uint32_t bW1 = sb + OFF_W1H + ((uint32_t)(nh * 64) + (bl & 7u)) * 256u;
    const uint32_t bW2 = sb + OFF_W2H + ((uint32_t)(nh * 32) + (bl & 7u)) * 256u;

    // epilogue row/col pieces
    const int erow = (l >> 2);               // 0..7
    const uint32_t e_xor = ((uint32_t)erow & 7u) << 4;

    // per-lane bias registers
    float bias1[8][2], bias2[4][2];
    {
        const float* B1s = (const float*)(S + OFF_B1);
        const float* B2s = (const float*)(S + OFF_B2);
        #pragma unroll
        for (int nt = 0; nt < 8; nt++) {
            int col = nh * 64 + nt * 8 + ccol;
            bias1[nt][0] = B1s[col];
            bias1[nt][1] = B1s[col + 1];
        }
        #pragma unroll
        for (int nt = 0; nt < 4; nt++) {
            int col = nh * 32 + nt * 8 + ccol;
            bias2[nt][0] = B2s[col];
            bias2[nt][1] = B2s[col + 1];
        }
    }

    int* sIdx = (int*)(S + OFF_IDX);
    float* stg = (float*)(S + OFF_STG);

    int nch = (count + 127) >> 7;
    for (int ch = blockIdx.x; ch < nch; ch += gridDim.x) {
        int base = ch << 7;

        // ---- gather + f32->f16 into swizzled A ----
        {
            int row = tid >> 1, h = tid & 1;
            int idx = base + row;
            bool valid = idx < count;
            const float4* src = nullptr;
            int scat = -1;
            if (valid) {
                if (which < 2) {
                    int eid = list[idx];
                    int rr, cc;
                    if (is64) { rr = (int)p64[eid]; cc = (int)p64[nE + eid]; }
                    else      { rr = p32[eid];      cc = p32[nE + eid]; }
                    scat = rr;
                    src = h ? (const float4*)(eattr + (size_t)eid * 64)
                            : (const float4*)(x + (size_t)cc * 64);
                } else {
                    scat = idx;
                    src = h ? (const float4*)(Bp + (size_t)idx * 64)
                            : (const float4*)(Ap + (size_t)idx * 64);
                }
            }
            if (h == 0) sIdx[row] = scat;
            #pragma unroll
            for (int j = 0; j < 16; j++) {
                float4 f = valid ? src[j] : make_float4(0.f, 0.f, 0.f, 0.f);
                __half2 p0 = __floats2half2_rn(f.x, f.y);
                __half2 p1 = __floats2half2_rn(f.z, f.w);
                uint2 v;
                v.x = *(uint32_t*)&p0;
                v.y = *(uint32_t*)&p1;
                *(uint2*)(S + OFF_A + SWZ(row, h * 128 + j * 8)) = v;
            }
        }
        __syncthreads();

        // ---- layer 1: 32m x 64n per warp, K=128, hi+lo passes ----
        {
            float acc[2][8][4];
            #pragma unroll
            for (int mt = 0; mt < 2; mt++)
                #pragma unroll
                for (int nt = 0; nt < 8; nt++) {
                    acc[mt][nt][0] = bias1[nt][0];
                    acc[mt][nt][1] = bias1[nt][1];
                    acc[mt][nt][2] = bias1[nt][0];
                    acc[mt][nt][3] = bias1[nt][1];
                }
            #pragma unroll
            for (int kt = 0; kt < 8; kt++) {
                uint32_t ka = (uint32_t)(kt * 32);
                uint32_t a0[4], a1[4];
                LDMX4(a0, aA + ((ka + a_cb16) ^ a_xor));
                LDMX4(a1, aA + 16u * 256u + ((ka + a_cb16) ^ a_xor));
                #pragma unroll
                for (int nt = 0; nt < 8; nt++) {
                    uint32_t baddr = bW1 + (uint32_t)(nt * 2048) + ((ka + b_cb16) ^ b_xor);
                    uint32_t bh[2], blo[2];
                    LDMX2(bh, baddr);
                    MMA16816(acc[0][nt], a0, bh);
                    MMA16816(acc[1][nt], a1, bh);
                    LDMX2(blo, baddr + 32768u);
                    MMA16816(acc[0][nt], a0, blo);
                    MMA16816(acc[1][nt], a1, blo);
                }
            }
            // epilogue 1: relu -> fp16 H1
            #pragma unroll
            for (int mt = 0; mt < 2; mt++) {
                uint32_t r0 = (uint32_t)(mbase + mt * 16 + erow);
                #pragma unroll
                for (int nt = 0; nt < 8; nt++) {
                    uint32_t cb = (uint32_t)((nh * 64 + nt * 8 + ccol) * 2);
                    __half2 h0 = __floats2half2_rn(fmaxf(acc[mt][nt][0], 0.f), fmaxf(acc[mt][nt][1], 0.f));
                    __half2 h1 = __floats2half2_rn(fmaxf(acc[mt][nt][2], 0.f), fmaxf(acc[mt][nt][3], 0.f));
                    *(uint32_t*)(S + OFF_H1 + r0 * 256u + (cb ^ e_xor)) = *(uint32_t*)&h0;
                    *(uint32_t*)(S + OFF_H1 + (r0 + 8u) * 256u + (cb ^ e_xor)) = *(uint32_t*)&h1;
                }
            }
        }
        __syncthreads();

        // ---- layer 2: 32m x 32n per warp, K=128, hi+lo ----
        {
            float acc[2][4][4];
            #pragma unroll
            for (int mt = 0; mt < 2; mt++)
                #pragma unroll
                for (int nt = 0; nt < 4; nt++) {
                    acc[mt][nt][0] = bias2[nt][0];
                    acc[mt][nt][1] = bias2[nt][1];
                    acc[mt][nt][2] = bias2[nt][0];
                    acc[mt][nt][3] = bias2[nt][1];
                }
            #pragma unroll
            for (int kt = 0; kt < 8; kt++) {
                uint32_t ka = (uint32_t)(kt * 32);
                uint32_t a0[4], a1[4];
                LDMX4(a0, aH + ((ka + a_cb16) ^ a_xor));
                LDMX4(a1, aH + 16u * 256u + ((ka + a_cb16) ^ a_xor));
                #pragma unroll
                for (int nt = 0; nt < 4; nt++) {
                    uint32_t baddr = bW2 + (uint32_t)(nt * 2048) + ((ka + b_cb16) ^ b_xor);
                    uint32_t bh[2], blo[2];
                    LDMX2(bh, baddr);
                    MMA16816(acc[0][nt], a0, bh);
                    MMA16816(acc[1][nt], a1, bh);
                    LDMX2(blo, baddr + 16384u);
                    MMA16816(acc[0][nt], a0, blo);
                    MMA16816(acc[1][nt], a1, blo);
                }
            }
            // stage relu(out) f32 to smem
            #pragma unroll
            for (int mt = 0; mt < 2; mt++) {
                int r0 = mbase + mt * 16 + erow;
                #pragma unroll
                for (int nt = 0; nt < 4; nt++) {
                    int col = nh * 32 + nt * 8 + ccol;
                    stg[r0 * 68 + col]           = fmaxf(acc[mt][nt][0], 0.f);
                    stg[r0 * 68 + col + 1]       = fmaxf(acc[mt][nt][1], 0.f);
                    stg[(r0 + 8) * 68 + col]     = fmaxf(acc[mt][nt][2], 0.f);
                    stg[(r0 + 8) * 68 + col + 1] = fmaxf(acc[mt][nt][3], 0.f);
                }
            }
        }
        __syncthreads();

        // ---- scatter: float4 vector atomics (or direct store for nodes) ----
        {
            int row = tid >> 1;
            int coff = (tid & 1) * 32;
            int node = sIdx[row];
            if (node >= 0) {
                const float* s = &stg[row * 68 + coff];
                if (which < 2) {
                    float4* dst = (float4*)(scatp + (size_t)node * 64 + coff);
                    #pragma unroll
                    for (int q = 0; q < 8; q++) {
                        float4 v = make_float4(s[4*q], s[4*q+1], s[4*q+2], s[4*q+3]);
                        atomicAdd(dst + q, v);
                    }
                } else {
                    float4* dst = (float4*)(nodeout + (size_t)node * 64 + coff);
                    #pragma unroll
                    for (int q = 0; q < 8; q++)
                        dst[q] = make_float4(s[4*q], s[4*q+1], s[4*q+2], s[4*q+3]);
                }
            }
        }
        __syncthreads();   // protect A/H1/stg/sIdx for next chunk
    }
}

// ---------------- launch ----------------
extern "C" void kernel_launch(void* const* d_in, const int* in_sizes, int n_in,
                              void* d_out, int out_size) {
    const float* x     = (const float*)d_in[0];
    const void*  eidx  = d_in[1];
    const float* eattr = (const float*)d_in[2];
    const float* Wo1 = (const float*)d_in[3];
    const float* bo1 = (const float*)d_in[4];
    const float* Wo2 = (const float*)d_in[5];
    const float* bo2 = (const float*)d_in[6];
    const float* Wi1 = (const float*)d_in[7];
    const float* bi1 = (const float*)d_in[8];
    const float* Wi2 = (const float*)d_in[9];
    const float* bi2 = (const float*)d_in[10];
    const float* Wn1 = (const float*)d_in[11];
    const float* bn1 = (const float*)d_in[12];
    const float* Wn2 = (const float*)d_in[13];
    const float* bn2 = (const float*)d_in[14];

    int nN = in_sizes[0] / 64;
    int nE = in_sizes[2] / 64;

    cudaFuncSetAttribute(mlp_tc_kernel, cudaFuncAttributeMaxDynamicSharedMemorySize, SMEM_TOTAL);

    int initBlocks = (nN * 16 + 255) / 256;
    init_kernel<<<initBlocks, 256>>>(eidx, nN);
    compact_kernel<<<(nE + 255) / 256, 256>>>(eidx, nE);

    mlp_tc_kernel<<<148, 256, SMEM_TOTAL>>>(0, nN, nE, x, eidx, eattr,
                                            Wo1, bo1, Wo2, bo2, nullptr);
    mlp_tc_kernel<<<148, 256, SMEM_TOTAL>>>(1, nN, nE, x, eidx, eattr,
                                            Wi1, bi1, Wi2, bi2, nullptr);
    mlp_tc_kernel<<<148, 256, SMEM_TOTAL>>>(2, nN, nE, x, eidx, eattr,
                                            Wn1, bn1, Wn2, bn2, (float*)d_out);
}

// round 6
// speedup vs baseline: 3.4146x; 1.3561x over previous
#include <cuda_runtime.h>
#include <cuda_fp16.h>
#include <stdint.h>

#define NN_MAX 50000
#define NE_MAX 800000

// ---------------- device scratch ----------------
__device__ float g_flow_in[NN_MAX * 64];
__device__ float g_flow_out[NN_MAX * 64];
__device__ int   g_out_list[NE_MAX];
__device__ int   g_in_list[NE_MAX];
__device__ int   g_counts[2];   // [0]=out (row<col), [1]=in (row>col)
__device__ int   g_is64;

// ---------------- smem layout (bytes) ----------------
// rows of 128 halfs = 256B, XOR-swizzled within row
#define OFF_W1  0         // 128n x 128k fp16   32KB
#define OFF_W2  32768     // 64n x 128k fp16    16KB
#define OFF_AH  49152     // 128m x 128k fp16   32KB (A, then reused for H1)
#define OFF_B1  81920     // 128 f32
#define OFF_B2  82432     // 64 f32
#define OFF_IDX 82688     // 128 int
#define SMEM_TOTAL 83200

// swizzle: byte offset within tile for (row, colbyte)
#define SWZ(row, cb) ((uint32_t)(row) * 256u + (((uint32_t)(cb)) ^ ((((uint32_t)(row)) & 7u) << 4)))

__device__ __forceinline__ uint32_t smem_u32(const void* p) {
    uint32_t a;
    asm("{ .reg .u64 t; cvta.to.shared.u64 t, %1; cvt.u32.u64 %0, t; }" : "=r"(a) : "l"(p));
    return a;
}

#define LDMX4(r, a) \
    asm volatile("ldmatrix.sync.aligned.m8n8.x4.shared.b16 {%0,%1,%2,%3}, [%4];" \
        : "=r"((r)[0]), "=r"((r)[1]), "=r"((r)[2]), "=r"((r)[3]) : "r"(a))
#define MMA16816(c, a, b0, b1) \
    asm volatile("mma.sync.aligned.m16n8k16.row.col.f32.f16.f16.f32 " \
        "{%0,%1,%2,%3}, {%4,%5,%6,%7}, {%8,%9}, {%0,%1,%2,%3};" \
        : "+f"((c)[0]), "+f"((c)[1]), "+f"((c)[2]), "+f"((c)[3]) \
        : "r"((a)[0]), "r"((a)[1]), "r"((a)[2]), "r"((a)[3]), "r"(b0), "r"(b1))

// ---------------- init ----------------
__global__ void init_kernel(const void* eidx, int nN) {
    int i = blockIdx.x * blockDim.x + threadIdx.x;
    float4 z = make_float4(0.f, 0.f, 0.f, 0.f);
    int total = nN * 16;
    if (i < total) {
        ((float4*)g_flow_in)[i]  = z;
        ((float4*)g_flow_out)[i] = z;
    }
    if (i == 0) {
        g_counts[0] = 0;
        g_counts[1] = 0;
        const int* w = (const int*)eidx;
        int nz = 0;
        #pragma unroll
        for (int k = 0; k < 32; k++) nz |= w[2 * k + 1];
        g_is64 = (nz == 0) ? 1 : 0;
    }
}

// ---------------- compaction ----------------
__global__ void compact_kernel(const void* eidx, int nE) {
    int e = blockIdx.x * blockDim.x + threadIdx.x;
    int lane = threadIdx.x & 31;
    bool is_out = false, is_in = false;
    if (e < nE) {
        int r, c;
        if (g_is64) {
            const long long* p = (const long long*)eidx;
            r = (int)p[e]; c = (int)p[nE + e];
        } else {
            const int* p = (const int*)eidx;
            r = p[e]; c = p[nE + e];
        }
        is_out = (r < c);
        is_in  = (r > c);
    }
    unsigned mo = __ballot_sync(0xffffffffu, is_out);
    unsigned mi = __ballot_sync(0xffffffffu, is_in);
    int bo = 0, bi = 0;
    if (lane == 0) {
        if (mo) bo = atomicAdd(&g_counts[0], __popc(mo));
        if (mi) bi = atomicAdd(&g_counts[1], __popc(mi));
    }
    bo = __shfl_sync(0xffffffffu, bo, 0);
    bi = __shfl_sync(0xffffffffu, bi, 0);
    unsigned lt = (1u << lane) - 1u;
    if (is_out) g_out_list[bo + __popc(mo & lt)] = e;
    if (is_in)  g_in_list [bi + __popc(mi & lt)] = e;
}

// ---------------- fused 2-layer MLP on mma.sync tensor cores ----------------
// which==0: edges (out list) -> atomic scatter g_flow_out[row]
// which==1: edges (in list)  -> atomic scatter g_flow_in[row]
// which==2: nodes, input = concat(flow_in, flow_out) -> store nodeout
__global__ void __launch_bounds__(256, 2)
mlp_tc_kernel(int which, int nN, int nE,
              const float* __restrict__ x, const void* __restrict__ eidx,
              const float* __restrict__ eattr,
              const float* __restrict__ W1, const float* __restrict__ b1,
              const float* __restrict__ W2, const float* __restrict__ b2,
              float* __restrict__ nodeout)
{
    extern __shared__ __align__(256) char smem[];
    char* S = smem;
    const uint32_t sb = smem_u32(smem);
    const int tid = threadIdx.x;
    const int wid = tid >> 5;
    const int l = tid & 31;

    // ---- stage weights: W^T fp16, swizzled [n][k] ----
    for (int i = tid; i < 128 * 128; i += 256) {
        int n = i >> 7, k = i & 127;
        *(__half*)(S + OFF_W1 + SWZ(n, k * 2)) = __float2half_rn(W1[k * 128 + n]);
    }
    for (int i = tid; i < 64 * 128; i += 256) {
        int n = i >> 7, k = i & 127;
        *(__half*)(S + OFF_W2 + SWZ(n, k * 2)) = __float2half_rn(W2[k * 64 + n]);
    }
    if (tid < 128) ((float*)(S + OFF_B1))[tid] = b1[tid];
    if (tid < 64)  ((float*)(S + OFF_B2))[tid] = b2[tid];

    // ---- mode setup ----
    int count;
    const int* list = nullptr;
    float* scatp = nullptr;
    const float* Ap = nullptr;
    const float* Bp = nullptr;
    if (which == 0)      { count = g_counts[0]; list = g_out_list; scatp = g_flow_out; }
    else if (which == 1) { count = g_counts[1]; list = g_in_list;  scatp = g_flow_in;  }
    else                 { count = nN; Ap = g_flow_in; Bp = g_flow_out; }
    const int is64 = g_is64;
    const long long* p64 = (const long long*)eidx;
    const int* p32 = (const int*)eidx;

    __syncthreads();

    // ---- per-lane constants ----
    const int mg = wid & 3;          // m-group: rows mg*32 .. +31
    const int nh = wid >> 2;         // n-half
    const int mbase = mg * 32;
    const int ccol = (l & 3) * 2;    // fragment column pair offset

    // A/H1 ldmatrix per-lane address pieces
    const uint32_t a_row  = (uint32_t)(mbase + (l & 15));
    const uint32_t a_cb16 = (uint32_t)((l >> 4) * 16);
    const uint32_t a_xor  = (a_row & 7u) << 4;
    const uint32_t aAH = sb + OFF_AH + a_row * 256u;

    // B ldmatrix x4 per-lane address pieces:
    // lanes 0-7: rows n..n+7 k-lo | 8-15: rows n..n+7 k-hi |
    // 16-23: rows n+8..n+15 k-lo | 24-31: rows n+8..n+15 k-hi
    const uint32_t b_rowoff = (uint32_t)(((l >> 4) << 3) + (l & 7));
    const uint32_t b_cb16   = ((uint32_t)(l >> 3) & 1u) * 16u;
    const uint32_t b_xor    = ((uint32_t)l & 7u) << 4;
    const uint32_t bW1 = sb + OFF_W1 + ((uint32_t)(nh * 64) + b_rowoff) * 256u;
    const uint32_t bW2 = sb + OFF_W2 + ((uint32_t)(nh * 32) + b_rowoff) * 256u;

    // epilogue row/col pieces
    const int erow = (l >> 2);               // 0..7
    const uint32_t e_xor = ((uint32_t)erow & 7u) << 4;

    // per-lane bias registers
    float bias1[8][2], bias2[4][2];
    {
        const float* B1s = (const float*)(S + OFF_B1);
        const float* B2s = (const float*)(S + OFF_B2);
        #pragma unroll
        for (int nt = 0; nt < 8; nt++) {
            int col = nh * 64 + nt * 8 + ccol;
            bias1[nt][0] = B1s[col];
            bias1[nt][1] = B1s[col + 1];
        }
        #pragma unroll
        for (int nt = 0; nt < 4; nt++) {
            int col = nh * 32 + nt * 8 + ccol;
            bias2[nt][0] = B2s[col];
            bias2[nt][1] = B2s[col + 1];
        }
    }

    int* sIdx = (int*)(S + OFF_IDX);

    int nch = (count + 127) >> 7;
    for (int ch = blockIdx.x; ch < nch; ch += gridDim.x) {
        int base = ch << 7;

        // ---- gather + f32->f16 into swizzled A (AH buffer) ----
        {
            int row = tid >> 1, h = tid & 1;
            int idx = base + row;
            bool valid = idx < count;
            const float4* src = nullptr;
            int scat = -1;
            if (valid) {
                if (which < 2) {
                    int eid = list[idx];
                    int rr, cc;
                    if (is64) { rr = (int)p64[eid]; cc = (int)p64[nE + eid]; }
                    else      { rr = p32[eid];      cc = p32[nE + eid]; }
                    scat = rr;
                    src = h ? (const float4*)(eattr + (size_t)eid * 64)
                            : (const float4*)(x + (size_t)cc * 64);
                } else {
                    scat = idx;
                    src = h ? (const float4*)(Bp + (size_t)idx * 64)
                            : (const float4*)(Ap + (size_t)idx * 64);
                }
            }
            if (h == 0) sIdx[row] = scat;
            #pragma unroll
            for (int j = 0; j < 16; j++) {
                float4 f = valid ? src[j] : make_float4(0.f, 0.f, 0.f, 0.f);
                __half2 p0 = __floats2half2_rn(f.x, f.y);
                __half2 p1 = __floats2half2_rn(f.z, f.w);
                uint2 v;
                v.x = *(uint32_t*)&p0;
                v.y = *(uint32_t*)&p1;
                *(uint2*)(S + OFF_AH + SWZ(row, h * 128 + j * 8)) = v;
            }
        }
        __syncthreads();

        // ---- layer 1: 32m x 64n per warp, K=128, single pass ----
        float acc1[2][8][4];
        #pragma unroll
        for (int mt = 0; mt < 2; mt++)
            #pragma unroll
            for (int nt = 0; nt < 8; nt++) {
                acc1[mt][nt][0] = bias1[nt][0];
                acc1[mt][nt][1] = bias1[nt][1];
                acc1[mt][nt][2] = bias1[nt][0];
                acc1[mt][nt][3] = bias1[nt][1];
            }
        #pragma unroll
        for (int kt = 0; kt < 8; kt++) {
            uint32_t ka = (uint32_t)(kt * 32);
            uint32_t a0[4], a1[4];
            LDMX4(a0, aAH + ((ka + a_cb16) ^ a_xor));
            LDMX4(a1, aAH + 16u * 256u + ((ka + a_cb16) ^ a_xor));
            #pragma unroll
            for (int np = 0; np < 4; np++) {
                uint32_t bfr[4];
                LDMX4(bfr, bW1 + (uint32_t)(np * 4096) + ((ka + b_cb16) ^ b_xor));
                MMA16816(acc1[0][2*np],   a0, bfr[0], bfr[1]);
                MMA16816(acc1[1][2*np],   a1, bfr[0], bfr[1]);
                MMA16816(acc1[0][2*np+1], a0, bfr[2], bfr[3]);
                MMA16816(acc1[1][2*np+1], a1, bfr[2], bfr[3]);
            }
        }
        __syncthreads();   // all warps done reading A before H1 overwrites it

        // ---- epilogue 1: relu -> fp16 H1 (into AH buffer) ----
        #pragma unroll
        for (int mt = 0; mt < 2; mt++) {
            uint32_t r0 = (uint32_t)(mbase + mt * 16 + erow);
            #pragma unroll
            for (int nt = 0; nt < 8; nt++) {
                uint32_t cb = (uint32_t)((nh * 64 + nt * 8 + ccol) * 2);
                __half2 h0 = __floats2half2_rn(fmaxf(acc1[mt][nt][0], 0.f), fmaxf(acc1[mt][nt][1], 0.f));
                __half2 h1 = __floats2half2_rn(fmaxf(acc1[mt][nt][2], 0.f), fmaxf(acc1[mt][nt][3], 0.f));
                *(uint32_t*)(S + OFF_AH + r0 * 256u + (cb ^ e_xor)) = *(uint32_t*)&h0;
                *(uint32_t*)(S + OFF_AH + (r0 + 8u) * 256u + (cb ^ e_xor)) = *(uint32_t*)&h1;
            }
        }
        __syncthreads();

        // ---- layer 2: 32m x 32n per warp, K=128, single pass ----
        {
            float acc2[2][4][4];
            #pragma unroll
            for (int mt = 0; mt < 2; mt++)
                #pragma unroll
                for (int nt = 0; nt < 4; nt++) {
                    acc2[mt][nt][0] = bias2[nt][0];
                    acc2[mt][nt][1] = bias2[nt][1];
                    acc2[mt][nt][2] = bias2[nt][0];
                    acc2[mt][nt][3] = bias2[nt][1];
                }
            #pragma unroll
            for (int kt = 0; kt < 8; kt++) {
                uint32_t ka = (uint32_t)(kt * 32);
                uint32_t a0[4], a1[4];
                LDMX4(a0, aAH + ((ka + a_cb16) ^ a_xor));
                LDMX4(a1, aAH + 16u * 256u + ((ka + a_cb16) ^ a_xor));
                #pragma unroll
                for (int np = 0; np < 2; np++) {
                    uint32_t bfr[4];
                    LDMX4(bfr, bW2 + (uint32_t)(np * 4096) + ((ka + b_cb16) ^ b_xor));
                    MMA16816(acc2[0][2*np],   a0, bfr[0], bfr[1]);
                    MMA16816(acc2[1][2*np],   a1, bfr[0], bfr[1]);
                    MMA16816(acc2[0][2*np+1], a0, bfr[2], bfr[3]);
                    MMA16816(acc2[1][2*np+1], a1, bfr[2], bfr[3]);
                }
            }

            // ---- epilogue 2: relu + direct vector-atomic scatter / store ----
            #pragma unroll
            for (int mt = 0; mt < 2; mt++) {
                int r0 = mbase + mt * 16 + erow;
                int n0 = sIdx[r0];
                int n1 = sIdx[r0 + 8];
                #pragma unroll
                for (int nt = 0; nt < 4; nt++) {
                    int col = nh * 32 + nt * 8 + ccol;
                    float2 vA = make_float2(fmaxf(acc2[mt][nt][0], 0.f), fmaxf(acc2[mt][nt][1], 0.f));
                    float2 vB = make_float2(fmaxf(acc2[mt][nt][2], 0.f), fmaxf(acc2[mt][nt][3], 0.f));
                    if (which < 2) {
                        if (n0 >= 0) atomicAdd((float2*)(scatp + (size_t)n0 * 64 + col), vA);
                        if (n1 >= 0) atomicAdd((float2*)(scatp + (size_t)n1 * 64 + col), vB);
                    } else {
                        if (n0 >= 0) *(float2*)(nodeout + (size_t)n0 * 64 + col) = vA;
                        if (n1 >= 0) *(float2*)(nodeout + (size_t)n1 * 64 + col) = vB;
                    }
                }
            }
        }
        __syncthreads();   // protect AH/sIdx for next chunk
    }
}

// ---------------- launch ----------------
extern "C" void kernel_launch(void* const* d_in, const int* in_sizes, int n_in,
                              void* d_out, int out_size) {
    const float* x     = (const float*)d_in[0];
    const void*  eidx  = d_in[1];
    const float* eattr = (const float*)d_in[2];
    const float* Wo1 = (const float*)d_in[3];
    const float* bo1 = (const float*)d_in[4];
    const float* Wo2 = (const float*)d_in[5];
    const float* bo2 = (const float*)d_in[6];
    const float* Wi1 = (const float*)d_in[7];
    const float* bi1 = (const float*)d_in[8];
    const float* Wi2 = (const float*)d_in[9];
    const float* bi2 = (const float*)d_in[10];
    const float* Wn1 = (const float*)d_in[11];
    const float* bn1 = (const float*)d_in[12];
    const float* Wn2 = (const float*)d_in[13];
    const float* bn2 = (const float*)d_in[14];

    int nN = in_sizes[0] / 64;
    int nE = in_sizes[2] / 64;

    cudaFuncSetAttribute(mlp_tc_kernel, cudaFuncAttributeMaxDynamicSharedMemorySize, SMEM_TOTAL);

    int initBlocks = (nN * 16 + 255) / 256;
    init_kernel<<<initBlocks, 256>>>(eidx, nN);
    compact_kernel<<<(nE + 255) / 256, 256>>>(eidx, nE);

    mlp_tc_kernel<<<296, 256, SMEM_TOTAL>>>(0, nN, nE, x, eidx, eattr,
                                            Wo1, bo1, Wo2, bo2, nullptr);
    mlp_tc_kernel<<<296, 256, SMEM_TOTAL>>>(1, nN, nE, x, eidx, eattr,
                                            Wi1, bi1, Wi2, bi2, nullptr);
    mlp_tc_kernel<<<296, 256, SMEM_TOTAL>>>(2, nN, nE, x, eidx, eattr,
                                            Wn1, bn1, Wn2, bn2, (float*)d_out);
}

// round 7
// speedup vs baseline: 3.8228x; 1.1195x over previous
#include <cuda_runtime.h>
#include <cuda_fp16.h>
#include <stdint.h>

#define NN_MAX 50000
#define NE_MAX 800000

// ---------------- device scratch ----------------
__device__ float g_flow_in[NN_MAX * 64];
__device__ float g_flow_out[NN_MAX * 64];
__device__ int   g_out_list[NE_MAX];
__device__ int   g_in_list[NE_MAX];
__device__ int   g_counts[2];   // [0]=out (row<col), [1]=in (row>col)
__device__ int   g_is64;

// ---------------- smem layout (bytes) ----------------
#define OFF_W1  0         // 128n x 128k fp16   32KB
#define OFF_W2  32768     // 64n x 128k fp16    16KB
#define OFF_AH  49152     // 128m x 128k fp16   32KB (A, then reused for H1)
#define OFF_B1  81920     // 128 f32
#define OFF_B2  82432     // 64 f32
#define OFF_IDX 82688     // 128 int
#define SMEM_TOTAL 83200

#define SWZ(row, cb) ((uint32_t)(row) * 256u + (((uint32_t)(cb)) ^ ((((uint32_t)(row)) & 7u) << 4)))

__device__ __forceinline__ uint32_t smem_u32(const void* p) {
    uint32_t a;
    asm("{ .reg .u64 t; cvta.to.shared.u64 t, %1; cvt.u32.u64 %0, t; }" : "=r"(a) : "l"(p));
    return a;
}

#define LDMX4(r, a) \
    asm volatile("ldmatrix.sync.aligned.m8n8.x4.shared.b16 {%0,%1,%2,%3}, [%4];" \
        : "=r"((r)[0]), "=r"((r)[1]), "=r"((r)[2]), "=r"((r)[3]) : "r"(a))
#define MMA16816(c, a, b0, b1) \
    asm volatile("mma.sync.aligned.m16n8k16.row.col.f32.f16.f16.f32 " \
        "{%0,%1,%2,%3}, {%4,%5,%6,%7}, {%8,%9}, {%0,%1,%2,%3};" \
        : "+f"((c)[0]), "+f"((c)[1]), "+f"((c)[2]), "+f"((c)[3]) \
        : "r"((a)[0]), "r"((a)[1]), "r"((a)[2]), "r"((a)[3]), "r"(b0), "r"(b1))

// ---------------- init ----------------
__global__ void init_kernel(const void* eidx, int nN) {
    int i = blockIdx.x * blockDim.x + threadIdx.x;
    float4 z = make_float4(0.f, 0.f, 0.f, 0.f);
    int total = nN * 16;
    if (i < total) {
        ((float4*)g_flow_in)[i]  = z;
        ((float4*)g_flow_out)[i] = z;
    }
    if (i == 0) {
        g_counts[0] = 0;
        g_counts[1] = 0;
        const int* w = (const int*)eidx;
        int nz = 0;
        #pragma unroll
        for (int k = 0; k < 32; k++) nz |= w[2 * k + 1];
        g_is64 = (nz == 0) ? 1 : 0;
    }
}

// ---------------- compaction ----------------
__global__ void compact_kernel(const void* eidx, int nE) {
    int e = blockIdx.x * blockDim.x + threadIdx.x;
    int lane = threadIdx.x & 31;
    bool is_out = false, is_in = false;
    if (e < nE) {
        int r, c;
        if (g_is64) {
            const long long* p = (const long long*)eidx;
            r = (int)p[e]; c = (int)p[nE + e];
        } else {
            const int* p = (const int*)eidx;
            r = p[e]; c = p[nE + e];
        }
        is_out = (r < c);
        is_in  = (r > c);
    }
    unsigned mo = __ballot_sync(0xffffffffu, is_out);
    unsigned mi = __ballot_sync(0xffffffffu, is_in);
    int bo = 0, bi = 0;
    if (lane == 0) {
        if (mo) bo = atomicAdd(&g_counts[0], __popc(mo));
        if (mi) bi = atomicAdd(&g_counts[1], __popc(mi));
    }
    bo = __shfl_sync(0xffffffffu, bo, 0);
    bi = __shfl_sync(0xffffffffu, bi, 0);
    unsigned lt = (1u << lane) - 1u;
    if (is_out) g_out_list[bo + __popc(mo & lt)] = e;
    if (is_in)  g_in_list [bi + __popc(mi & lt)] = e;
}

// ---------------- fused 2-layer MLP on mma.sync tensor cores ----------------
// which==3: merged edge kernel; CTAs [0,G/2) process out-list, [G/2,G) in-list
// which==2: nodes, input = concat(flow_in, flow_out) -> store nodeout
__global__ void __launch_bounds__(256, 2)
mlp_tc_kernel(int which, int nN, int nE,
              const float* __restrict__ x, const void* __restrict__ eidx,
              const float* __restrict__ eattr,
              const float* __restrict__ WA1, const float* __restrict__ bA1,
              const float* __restrict__ WA2, const float* __restrict__ bA2,
              const float* __restrict__ WB1, const float* __restrict__ bB1,
              const float* __restrict__ WB2, const float* __restrict__ bB2,
              float* __restrict__ nodeout)
{
    extern __shared__ __align__(256) char smem[];
    char* S = smem;
    const uint32_t sb = smem_u32(smem);
    const int tid = threadIdx.x;
    const int wid = tid >> 5;
    const int l = tid & 31;

    // ---- mode select ----
    int w, ctaoff, cstride;
    if (which == 3) {
        int halfg = gridDim.x >> 1;
        w = (blockIdx.x >= halfg) ? 1 : 0;
        ctaoff = blockIdx.x - w * halfg;
        cstride = halfg;
    } else {
        w = 2;
        ctaoff = blockIdx.x;
        cstride = gridDim.x;
    }
    const float* W1 = (w == 1) ? WB1 : WA1;
    const float* b1 = (w == 1) ? bB1 : bA1;
    const float* W2 = (w == 1) ? WB2 : WA2;
    const float* b2 = (w == 1) ? bB2 : bA2;

    // ---- stage weights: W^T fp16, swizzled [n][k] ----
    for (int i = tid; i < 128 * 128; i += 256) {
        int n = i >> 7, k = i & 127;
        *(__half*)(S + OFF_W1 + SWZ(n, k * 2)) = __float2half_rn(W1[k * 128 + n]);
    }
    for (int i = tid; i < 64 * 128; i += 256) {
        int n = i >> 7, k = i & 127;
        *(__half*)(S + OFF_W2 + SWZ(n, k * 2)) = __float2half_rn(W2[k * 64 + n]);
    }
    if (tid < 128) ((float*)(S + OFF_B1))[tid] = b1[tid];
    if (tid < 64)  ((float*)(S + OFF_B2))[tid] = b2[tid];

    int count;
    const int* list = nullptr;
    float* scatp = nullptr;
    const float* Ap = nullptr;
    const float* Bp = nullptr;
    if (w == 0)      { count = g_counts[0]; list = g_out_list; scatp = g_flow_out; }
    else if (w == 1) { count = g_counts[1]; list = g_in_list;  scatp = g_flow_in;  }
    else             { count = nN; Ap = g_flow_in; Bp = g_flow_out; }
    const int is64 = g_is64;
    const long long* p64 = (const long long*)eidx;
    const int* p32 = (const int*)eidx;

    __syncthreads();

    // ---- per-lane constants ----
    const int mg = wid & 3;
    const int nh = wid >> 2;
    const int mbase = mg * 32;
    const int ccol = (l & 3) * 2;

    const uint32_t a_row  = (uint32_t)(mbase + (l & 15));
    const uint32_t a_cb16 = (uint32_t)((l >> 4) * 16);
    const uint32_t a_xor  = (a_row & 7u) << 4;
    const uint32_t aAH = sb + OFF_AH + a_row * 256u;

    const uint32_t b_rowoff = (uint32_t)(((l >> 4) << 3) + (l & 7));
    const uint32_t b_cb16   = ((uint32_t)(l >> 3) & 1u) * 16u;
    const uint32_t b_xor    = ((uint32_t)l & 7u) << 4;
    const uint32_t bW1 = sb + OFF_W1 + ((uint32_t)(nh * 64) + b_rowoff) * 256u;
    const uint32_t bW2 = sb + OFF_W2 + ((uint32_t)(nh * 32) + b_rowoff) * 256u;

    const int erow = (l >> 2);
    const uint32_t e_xor = ((uint32_t)erow & 7u) << 4;

    float bias1[8][2], bias2[4][2];
    {
        const float* B1s = (const float*)(S + OFF_B1);
        const float* B2s = (const float*)(S + OFF_B2);
        #pragma unroll
        for (int nt = 0; nt < 8; nt++) {
            int col = nh * 64 + nt * 8 + ccol;
            bias1[nt][0] = B1s[col];
            bias1[nt][1] = B1s[col + 1];
        }
        #pragma unroll
        for (int nt = 0; nt < 4; nt++) {
            int col = nh * 32 + nt * 8 + ccol;
            bias2[nt][0] = B2s[col];
            bias2[nt][1] = B2s[col + 1];
        }
    }

    int* sIdx = (int*)(S + OFF_IDX);

    // gather constants: 8 threads/row, 2 sources x 4 parts
    const int g_half = (tid >> 2) & 1;
    const int g_part = tid & 3;

    int nch = (count + 127) >> 7;
    for (int ch = ctaoff; ch < nch; ch += cstride) {
        int base = ch << 7;

        // ---- coalesced gather + f32->f16 into swizzled A ----
        #pragma unroll
        for (int pass = 0; pass < 4; pass++) {
            int r = pass * 32 + (tid >> 3);
            int idx = base + r;
            bool valid = idx < count;
            const float4* src = nullptr;
            int scat = -1;
            if (valid) {
                if (w < 2) {
                    int eid = list[idx];
                    int rr, cc;
                    if (is64) { rr = (int)p64[eid]; cc = (int)p64[nE + eid]; }
                    else      { rr = p32[eid];      cc = p32[nE + eid]; }
                    scat = rr;
                    src = g_half ? (const float4*)(eattr + (size_t)eid * 64)
                                 : (const float4*)(x + (size_t)cc * 64);
                } else {
                    scat = idx;
                    src = g_half ? (const float4*)(Bp + (size_t)idx * 64)
                                 : (const float4*)(Ap + (size_t)idx * 64);
                }
            }
            if ((tid & 7) == 0) sIdx[r] = scat;
            #pragma unroll
            for (int j = 0; j < 4; j++) {
                float4 f = valid ? src[g_part + 4 * j] : make_float4(0.f, 0.f, 0.f, 0.f);
                __half2 p0 = __floats2half2_rn(f.x, f.y);
                __half2 p1 = __floats2half2_rn(f.z, f.w);
                uint2 v;
                v.x = *(uint32_t*)&p0;
                v.y = *(uint32_t*)&p1;
                *(uint2*)(S + OFF_AH + SWZ(r, g_half * 128 + (g_part + 4 * j) * 8)) = v;
            }
        }
        __syncthreads();

        // ---- layer 1: 32m x 64n per warp, K=128 ----
        float acc1[2][8][4];
        #pragma unroll
        for (int mt = 0; mt < 2; mt++)
            #pragma unroll
            for (int nt = 0; nt < 8; nt++) {
                acc1[mt][nt][0] = bias1[nt][0];
                acc1[mt][nt][1] = bias1[nt][1];
                acc1[mt][nt][2] = bias1[nt][0];
                acc1[mt][nt][3] = bias1[nt][1];
            }
        #pragma unroll
        for (int kt = 0; kt < 8; kt++) {
            uint32_t ka = (uint32_t)(kt * 32);
            uint32_t a0[4], a1[4];
            LDMX4(a0, aAH + ((ka + a_cb16) ^ a_xor));
            LDMX4(a1, aAH + 16u * 256u + ((ka + a_cb16) ^ a_xor));
            #pragma unroll
            for (int np = 0; np < 4; np++) {
                uint32_t bfr[4];
                LDMX4(bfr, bW1 + (uint32_t)(np * 4096) + ((ka + b_cb16) ^ b_xor));
                MMA16816(acc1[0][2*np],   a0, bfr[0], bfr[1]);
                MMA16816(acc1[1][2*np],   a1, bfr[0], bfr[1]);
                MMA16816(acc1[0][2*np+1], a0, bfr[2], bfr[3]);
                MMA16816(acc1[1][2*np+1], a1, bfr[2], bfr[3]);
            }
        }
        __syncthreads();

        // ---- epilogue 1: relu -> fp16 H1 (into AH buffer) ----
        #pragma unroll
        for (int mt = 0; mt < 2; mt++) {
            uint32_t r0 = (uint32_t)(mbase + mt * 16 + erow);
            #pragma unroll
            for (int nt = 0; nt < 8; nt++) {
                uint32_t cb = (uint32_t)((nh * 64 + nt * 8 + ccol) * 2);
                __half2 h0 = __floats2half2_rn(fmaxf(acc1[mt][nt][0], 0.f), fmaxf(acc1[mt][nt][1], 0.f));
                __half2 h1 = __floats2half2_rn(fmaxf(acc1[mt][nt][2], 0.f), fmaxf(acc1[mt][nt][3], 0.f));
                *(uint32_t*)(S + OFF_AH + r0 * 256u + (cb ^ e_xor)) = *(uint32_t*)&h0;
                *(uint32_t*)(S + OFF_AH + (r0 + 8u) * 256u + (cb ^ e_xor)) = *(uint32_t*)&h1;
            }
        }
        __syncthreads();

        // ---- layer 2: 32m x 32n per warp, K=128 ----
        {
            float acc2[2][4][4];
            #pragma unroll
            for (int mt = 0; mt < 2; mt++)
                #pragma unroll
                for (int nt = 0; nt < 4; nt++) {
                    acc2[mt][nt][0] = bias2[nt][0];
                    acc2[mt][nt][1] = bias2[nt][1];
                    acc2[mt][nt][2] = bias2[nt][0];
                    acc2[mt][nt][3] = bias2[nt][1];
                }
            #pragma unroll
            for (int kt = 0; kt < 8; kt++) {
                uint32_t ka = (uint32_t)(kt * 32);
                uint32_t a0[4], a1[4];
                LDMX4(a0, aAH + ((ka + a_cb16) ^ a_xor));
                LDMX4(a1, aAH + 16u * 256u + ((ka + a_cb16) ^ a_xor));
                #pragma unroll
                for (int np = 0; np < 2; np++) {
                    uint32_t bfr[4];
                    LDMX4(bfr, bW2 + (uint32_t)(np * 4096) + ((ka + b_cb16) ^ b_xor));
                    MMA16816(acc2[0][2*np],   a0, bfr[0], bfr[1]);
                    MMA16816(acc2[1][2*np],   a1, bfr[0], bfr[1]);
                    MMA16816(acc2[0][2*np+1], a0, bfr[2], bfr[3]);
                    MMA16816(acc2[1][2*np+1], a1, bfr[2], bfr[3]);
                }
            }

            // ---- epilogue 2: relu + shuffle-pair into float4 + scatter ----
            // even lane -> row r0 (its c0,c1 + neighbor's c0,c1)
            // odd lane  -> row r0+8 (neighbor's c2,c3 + its c2,c3)
            const int cbase = nh * 32 + 4 * ((l >> 1) & 1);
            #pragma unroll
            for (int mt = 0; mt < 2; mt++) {
                int r0 = mbase + mt * 16 + erow;
                int myrow = r0 + ((l & 1) << 3);
                int node = sIdx[myrow];
                #pragma unroll
                for (int nt = 0; nt < 4; nt++) {
                    float v0 = fmaxf(acc2[mt][nt][0], 0.f);
                    float v1 = fmaxf(acc2[mt][nt][1], 0.f);
                    float v2 = fmaxf(acc2[mt][nt][2], 0.f);
                    float v3 = fmaxf(acc2[mt][nt][3], 0.f);
                    float s0 = __shfl_xor_sync(0xffffffffu, v0, 1);
                    float s1 = __shfl_xor_sync(0xffffffffu, v1, 1);
                    float s2 = __shfl_xor_sync(0xffffffffu, v2, 1);
                    float s3 = __shfl_xor_sync(0xffffffffu, v3, 1);
                    float4 q = (l & 1) ? make_float4(s2, s3, v2, v3)
                                       : make_float4(v0, v1, s0, s1);
                    if (node >= 0) {
                        int col = cbase + nt * 8;
                        if (w < 2)
                            atomicAdd((float4*)(scatp + (size_t)node * 64 + col), q);
                        else
                            *(float4*)(nodeout + (size_t)node * 64 + col) = q;
                    }
                }
            }
        }
        __syncthreads();   // protect AH/sIdx for next chunk
    }
}

// ---------------- launch ----------------
extern "C" void kernel_launch(void* const* d_in, const int* in_sizes, int n_in,
                              void* d_out, int out_size) {
    const float* x     = (const float*)d_in[0];
    const void*  eidx  = d_in[1];
    const float* eattr = (const float*)d_in[2];
    const float* Wo1 = (const float*)d_in[3];
    const float* bo1 = (const float*)d_in[4];
    const float* Wo2 = (const float*)d_in[5];
    const float* bo2 = (const float*)d_in[6];
    const float* Wi1 = (const float*)d_in[7];
    const float* bi1 = (const float*)d_in[8];
    const float* Wi2 = (const float*)d_in[9];
    const float* bi2 = (const float*)d_in[10];
    const float* Wn1 = (const float*)d_in[11];
    const float* bn1 = (const float*)d_in[12];
    const float* Wn2 = (const float*)d_in[13];
    const float* bn2 = (const float*)d_in[14];

    int nN = in_sizes[0] / 64;
    int nE = in_sizes[2] / 64;

    cudaFuncSetAttribute(mlp_tc_kernel, cudaFuncAttributeMaxDynamicSharedMemorySize, SMEM_TOTAL);

    int initBlocks = (nN * 16 + 255) / 256;
    init_kernel<<<initBlocks, 256>>>(eidx, nN);
    compact_kernel<<<(nE + 255) / 256, 256>>>(eidx, nE);

    // merged edge passes: CTAs 0-295 -> flow_out, 296-591 -> flow_in
    mlp_tc_kernel<<<592, 256, SMEM_TOTAL>>>(3, nN, nE, x, eidx, eattr,
                                            Wo1, bo1, Wo2, bo2,
                                            Wi1, bi1, Wi2, bi2, nullptr);
    // node MLP
    mlp_tc_kernel<<<296, 256, SMEM_TOTAL>>>(2, nN, nE, x, eidx, eattr,
                                            Wn1, bn1, Wn2, bn2,
                                            Wn1, bn1, Wn2, bn2, (float*)d_out);
}

// round 9
// speedup vs baseline: 3.9775x; 1.0405x over previous
#include <cuda_runtime.h>
#include <cuda_fp16.h>
#include <stdint.h>

#define NN_MAX 50000
#define NE_MAX 800000
#define GRID 296          // 148 SMs x 2 CTAs — exactly one resident wave

// ---------------- device scratch ----------------
__device__ float g_flow_in[NN_MAX * 64];
__device__ float g_flow_out[NN_MAX * 64];
__device__ int   g_out_list[NE_MAX];
__device__ int   g_in_list[NE_MAX];
__device__ int   g_counts[2];
__device__ int   g_is64;
__device__ unsigned g_cnt[3];    // monotonic barrier counters (never reset)

// ---------------- smem layout (bytes) ----------------
#define OFF_W1  0         // 128n x 128k fp16   32KB
#define OFF_W2  32768     // 64n x 128k fp16    16KB
#define OFF_AH  49152     // 128m x 128k fp16   32KB (A, then reused for H1)
#define OFF_B1  81920     // 128 f32
#define OFF_B2  82432     // 64 f32
#define OFF_IDX 82688     // 128 int
#define SMEM_TOTAL 83200

#define SWZ(row, cb) ((uint32_t)(row) * 256u + (((uint32_t)(cb)) ^ ((((uint32_t)(row)) & 7u) << 4)))

__device__ __forceinline__ uint32_t smem_u32(const void* p) {
    uint32_t a;
    asm("{ .reg .u64 t; cvta.to.shared.u64 t, %1; cvt.u32.u64 %0, t; }" : "=r"(a) : "l"(p));
    return a;
}

#define LDMX4(r, a) \
    asm volatile("ldmatrix.sync.aligned.m8n8.x4.shared.b16 {%0,%1,%2,%3}, [%4];" \
        : "=r"((r)[0]), "=r"((r)[1]), "=r"((r)[2]), "=r"((r)[3]) : "r"(a))
#define MMA16816(c, a, b0, b1) \
    asm volatile("mma.sync.aligned.m16n8k16.row.col.f32.f16.f16.f32 " \
        "{%0,%1,%2,%3}, {%4,%5,%6,%7}, {%8,%9}, {%0,%1,%2,%3};" \
        : "+f"((c)[0]), "+f"((c)[1]), "+f"((c)[2]), "+f"((c)[3]) \
        : "r"((a)[0]), "r"((a)[1]), "r"((a)[2]), "r"((a)[3]), "r"(b0), "r"(b1))

// ---------------- device-wide monotonic barrier ----------------
// All GRID CTAs are co-resident (one wave), so spinning is deadlock-free.
// Counter only ever increments; launches serialize, so each launch's cohort
// is a contiguous block of gridDim.x increments. No resets, no flags, no
// cross-launch state invariants.
__device__ __forceinline__ void grid_barrier(int i) {
    __syncthreads();
    if (threadIdx.x == 0) {
        __threadfence();
        unsigned old = atomicAdd(&g_cnt[i], 1u);
        unsigned target = old - (old % gridDim.x) + gridDim.x;
        while (atomicAdd(&g_cnt[i], 0u) < target) __nanosleep(64);
    }
    __syncthreads();
}

// ---------------- weight staging ----------------
__device__ __forceinline__ void stage_weights(char* S, int tid,
        const float* __restrict__ W1, const float* __restrict__ b1,
        const float* __restrict__ W2, const float* __restrict__ b2) {
    for (int i = tid; i < 128 * 128; i += 256) {
        int n = i >> 7, k = i & 127;
        *(__half*)(S + OFF_W1 + SWZ(n, k * 2)) = __float2half_rn(W1[k * 128 + n]);
    }
    for (int i = tid; i < 64 * 128; i += 256) {
        int n = i >> 7, k = i & 127;
        *(__half*)(S + OFF_W2 + SWZ(n, k * 2)) = __float2half_rn(W2[k * 64 + n]);
    }
    if (tid < 128) ((float*)(S + OFF_B1))[tid] = b1[tid];
    if (tid < 64)  ((float*)(S + OFF_B2))[tid] = b2[tid];
}

// ---------------- fused 2-layer MLP chunk loop (R7 proven body) ----------------
__device__ __forceinline__ void run_mlp(
    char* S, uint32_t sb, int tid, int wid, int l,
    int w, int count, const int* __restrict__ list, float* __restrict__ scatp,
    const float* __restrict__ Ap, const float* __restrict__ Bp,
    const float* __restrict__ x, const float* __restrict__ eattr,
    const long long* __restrict__ p64, const int* __restrict__ p32,
    int is64, int nE, int ctaoff, int cstride, float* __restrict__ nodeout)
{
    const int mg = wid & 3;
    const int nh = wid >> 2;
    const int mbase = mg * 32;
    const int ccol = (l & 3) * 2;

    const uint32_t a_row  = (uint32_t)(mbase + (l & 15));
    const uint32_t a_cb16 = (uint32_t)((l >> 4) * 16);
    const uint32_t a_xor  = (a_row & 7u) << 4;
    const uint32_t aAH = sb + OFF_AH + a_row * 256u;

    const uint32_t b_rowoff = (uint32_t)(((l >> 4) << 3) + (l & 7));
    const uint32_t b_cb16   = ((uint32_t)(l >> 3) & 1u) * 16u;
    const uint32_t b_xor    = ((uint32_t)l & 7u) << 4;
    const uint32_t bW1 = sb + OFF_W1 + ((uint32_t)(nh * 64) + b_rowoff) * 256u;
    const uint32_t bW2 = sb + OFF_W2 + ((uint32_t)(nh * 32) + b_rowoff) * 256u;

    const int erow = (l >> 2);
    const uint32_t e_xor = ((uint32_t)erow & 7u) << 4;

    float bias1[8][2], bias2[4][2];
    {
        const float* B1s = (const float*)(S + OFF_B1);
        const float* B2s = (const float*)(S + OFF_B2);
        #pragma unroll
        for (int nt = 0; nt < 8; nt++) {
            int col = nh * 64 + nt * 8 + ccol;
            bias1[nt][0] = B1s[col];
            bias1[nt][1] = B1s[col + 1];
        }
        #pragma unroll
        for (int nt = 0; nt < 4; nt++) {
            int col = nh * 32 + nt * 8 + ccol;
            bias2[nt][0] = B2s[col];
            bias2[nt][1] = B2s[col + 1];
        }
    }

    int* sIdx = (int*)(S + OFF_IDX);
    const int g_half = (tid >> 2) & 1;
    const int g_part = tid & 3;

    int nch = (count + 127) >> 7;
    for (int ch = ctaoff; ch < nch; ch += cstride) {
        int base = ch << 7;

        // ---- coalesced gather + f32->f16 into swizzled A ----
        #pragma unroll
        for (int pass = 0; pass < 4; pass++) {
            int r = pass * 32 + (tid >> 3);
            int idx = base + r;
            bool valid = idx < count;
            const float4* src = nullptr;
            int scat = -1;
            if (valid) {
                if (w < 2) {
                    int eid = list[idx];
                    int rr, cc;
                    if (is64) { rr = (int)p64[eid]; cc = (int)p64[nE + eid]; }
                    else      { rr = p32[eid];      cc = p32[nE + eid]; }
                    scat = rr;
                    src = g_half ? (const float4*)(eattr + (size_t)eid * 64)
                                 : (const float4*)(x + (size_t)cc * 64);
                } else {
                    scat = idx;
                    src = g_half ? (const float4*)(Bp + (size_t)idx * 64)
                                 : (const float4*)(Ap + (size_t)idx * 64);
                }
            }
            if ((tid & 7) == 0) sIdx[r] = scat;
            #pragma unroll
            for (int j = 0; j < 4; j++) {
                float4 f;
                if (valid) {
                    f = (w == 2) ? __ldcg(&src[g_part + 4 * j]) : __ldg(&src[g_part + 4 * j]);
                } else {
                    f = make_float4(0.f, 0.f, 0.f, 0.f);
                }
                __half2 p0 = __floats2half2_rn(f.x, f.y);
                __half2 p1 = __floats2half2_rn(f.z, f.w);
                uint2 v;
                v.x = *(uint32_t*)&p0;
                v.y = *(uint32_t*)&p1;
                *(uint2*)(S + OFF_AH + SWZ(r, g_half * 128 + (g_part + 4 * j) * 8)) = v;
            }
        }
        __syncthreads();

        // ---- layer 1: 32m x 64n per warp, K=128 ----
        float acc1[2][8][4];
        #pragma unroll
        for (int mt = 0; mt < 2; mt++)
            #pragma unroll
            for (int nt = 0; nt < 8; nt++) {
                acc1[mt][nt][0] = bias1[nt][0];
                acc1[mt][nt][1] = bias1[nt][1];
                acc1[mt][nt][2] = bias1[nt][0];
                acc1[mt][nt][3] = bias1[nt][1];
            }
        #pragma unroll
        for (int kt = 0; kt < 8; kt++) {
            uint32_t ka = (uint32_t)(kt * 32);
            uint32_t a0[4], a1[4];
            LDMX4(a0, aAH + ((ka + a_cb16) ^ a_xor));
            LDMX4(a1, aAH + 16u * 256u + ((ka + a_cb16) ^ a_xor));
            #pragma unroll
            for (int np = 0; np < 4; np++) {
                uint32_t bfr[4];
                LDMX4(bfr, bW1 + (uint32_t)(np * 4096) + ((ka + b_cb16) ^ b_xor));
                MMA16816(acc1[0][2*np],   a0, bfr[0], bfr[1]);
                MMA16816(acc1[1][2*np],   a1, bfr[0], bfr[1]);
                MMA16816(acc1[0][2*np+1], a0, bfr[2], bfr[3]);
                MMA16816(acc1[1][2*np+1], a1, bfr[2], bfr[3]);
            }
        }
        __syncthreads();

        // ---- epilogue 1: relu -> fp16 H1 (into AH buffer) ----
        #pragma unroll
        for (int mt = 0; mt < 2; mt++) {
            uint32_t r0 = (uint32_t)(mbase + mt * 16 + erow);
            #pragma unroll
            for (int nt = 0; nt < 8; nt++) {
                uint32_t cb = (uint32_t)((nh * 64 + nt * 8 + ccol) * 2);
                __half2 h0 = __floats2half2_rn(fmaxf(acc1[mt][nt][0], 0.f), fmaxf(acc1[mt][nt][1], 0.f));
                __half2 h1 = __floats2half2_rn(fmaxf(acc1[mt][nt][2], 0.f), fmaxf(acc1[mt][nt][3], 0.f));
                *(uint32_t*)(S + OFF_AH + r0 * 256u + (cb ^ e_xor)) = *(uint32_t*)&h0;
                *(uint32_t*)(S + OFF_AH + (r0 + 8u) * 256u + (cb ^ e_xor)) = *(uint32_t*)&h1;
            }
        }
        __syncthreads();

        // ---- layer 2: 32m x 32n per warp, K=128 ----
        {
            float acc2[2][4][4];
            #pragma unroll
            for (int mt = 0; mt < 2; mt++)
                #pragma unroll
                for (int nt = 0; nt < 4; nt++) {
                    acc2[mt][nt][0] = bias2[nt][0];
                    acc2[mt][nt][1] = bias2[nt][1];
                    acc2[mt][nt][2] = bias2[nt][0];
                    acc2[mt][nt][3] = bias2[nt][1];
                }
            #pragma unroll
            for (int kt = 0; kt < 8; kt++) {
                uint32_t ka = (uint32_t)(kt * 32);
                uint32_t a0[4], a1[4];
                LDMX4(a0, aAH + ((ka + a_cb16) ^ a_xor));
                LDMX4(a1, aAH + 16u * 256u + ((ka + a_cb16) ^ a_xor));
                #pragma unroll
                for (int np = 0; np < 2; np++) {
                    uint32_t bfr[4];
                    LDMX4(bfr, bW2 + (uint32_t)(np * 4096) + ((ka + b_cb16) ^ b_xor));
                    MMA16816(acc2[0][2*np],   a0, bfr[0], bfr[1]);
                    MMA16816(acc2[1][2*np],   a1, bfr[0], bfr[1]);
                    MMA16816(acc2[0][2*np+1], a0, bfr[2], bfr[3]);
                    MMA16816(acc2[1][2*np+1], a1, bfr[2], bfr[3]);
                }
            }

            // ---- epilogue 2: relu + shuffle-pair into float4 + scatter ----
            const int cbase = nh * 32 + 4 * ((l >> 1) & 1);
            #pragma unroll
            for (int mt = 0; mt < 2; mt++) {
                int r0 = mbase + mt * 16 + erow;
                int myrow = r0 + ((l & 1) << 3);
                int node = sIdx[myrow];
                #pragma unroll
                for (int nt = 0; nt < 4; nt++) {
                    float v0 = fmaxf(acc2[mt][nt][0], 0.f);
                    float v1 = fmaxf(acc2[mt][nt][1], 0.f);
                    float v2 = fmaxf(acc2[mt][nt][2], 0.f);
                    float v3 = fmaxf(acc2[mt][nt][3], 0.f);
                    float s0 = __shfl_xor_sync(0xffffffffu, v0, 1);
                    float s1 = __shfl_xor_sync(0xffffffffu, v1, 1);
                    float s2 = __shfl_xor_sync(0xffffffffu, v2, 1);
                    float s3 = __shfl_xor_sync(0xffffffffu, v3, 1);
                    float4 q = (l & 1) ? make_float4(s2, s3, v2, v3)
                                       : make_float4(v0, v1, s0, s1);
                    if (node >= 0) {
                        int col = cbase + nt * 8;
                        if (w < 2)
                            atomicAdd((float4*)(scatp + (size_t)node * 64 + col), q);
                        else
                            *(float4*)(nodeout + (size_t)node * 64 + col) = q;
                    }
                }
            }
        }
        __syncthreads();
    }
}

// ---------------- single persistent kernel ----------------
__global__ void __launch_bounds__(256, 2)
fused_kernel(int nN, int nE,
             const float* __restrict__ x, const void* __restrict__ eidx,
             const float* __restrict__ eattr,
             const float* __restrict__ Wo1, const float* __restrict__ bo1,
             const float* __restrict__ Wo2, const float* __restrict__ bo2,
             const float* __restrict__ Wi1, const float* __restrict__ bi1,
             const float* __restrict__ Wi2, const float* __restrict__ bi2,
             const float* __restrict__ Wn1, const float* __restrict__ bn1,
             const float* __restrict__ Wn2, const float* __restrict__ bn2,
             float* __restrict__ nodeout)
{
    extern __shared__ __align__(256) char smem[];
    char* S = smem;
    const uint32_t sb = smem_u32(smem);
    const int tid = threadIdx.x;
    const int wid = tid >> 5;
    const int l = tid & 31;
    const long long* p64 = (const long long*)eidx;
    const int* p32 = (const int*)eidx;

    // edge-direction for this CTA; stage edge weights (overlaps phases 0-1)
    const int w = blockIdx.x & 1;
    stage_weights(S, tid,
                  w ? Wi1 : Wo1, w ? bi1 : bo1,
                  w ? Wi2 : Wo2, w ? bi2 : bo2);

    // ---- phase 0: zero flows, reset counts, detect index dtype ----
    {
        int total = nN * 16;
        int stride = gridDim.x * 256;
        float4 z = make_float4(0.f, 0.f, 0.f, 0.f);
        for (int i = blockIdx.x * 256 + tid; i < total; i += stride) {
            ((float4*)g_flow_in)[i]  = z;
            ((float4*)g_flow_out)[i] = z;
        }
        if (blockIdx.x == 0 && tid == 0) {
            g_counts[0] = 0;
            g_counts[1] = 0;
            const int* wds = (const int*)eidx;
            int nz = 0;
            #pragma unroll
            for (int k = 0; k < 32; k++) nz |= wds[2 * k + 1];
            g_is64 = (nz == 0) ? 1 : 0;
        }
    }
    grid_barrier(0);
    const int is64 = g_is64;

    // ---- phase 1: compaction (warp-uniform grid-stride) ----
    {
        int stride = gridDim.x * 256;
        for (int e0 = blockIdx.x * 256 + wid * 32; e0 < nE; e0 += stride) {
            int e = e0 + l;
            bool is_out = false, is_in = false;
            if (e < nE) {
                int r, c;
                if (is64) { r = (int)p64[e]; c = (int)p64[nE + e]; }
                else      { r = p32[e];      c = p32[nE + e]; }
                is_out = (r < c);
                is_in  = (r > c);
            }
            unsigned mo = __ballot_sync(0xffffffffu, is_out);
            unsigned mi = __ballot_sync(0xffffffffu, is_in);
            int bo = 0, bi = 0;
            if (l == 0) {
                if (mo) bo = atomicAdd(&g_counts[0], __popc(mo));
                if (mi) bi = atomicAdd(&g_counts[1], __popc(mi));
            }
            bo = __shfl_sync(0xffffffffu, bo, 0);
            bi = __shfl_sync(0xffffffffu, bi, 0);
            unsigned lt = (1u << l) - 1u;
            if (is_out) g_out_list[bo + __popc(mo & lt)] = e;
            if (is_in)  g_in_list [bi + __popc(mi & lt)] = e;
        }
    }
    grid_barrier(1);

    // ---- phase 2: edge MLPs (even CTAs: out-list, odd CTAs: in-list) ----
    {
        int count = g_counts[w];
        const int* list = w ? g_in_list : g_out_list;
        float* scatp = w ? g_flow_in : g_flow_out;
        run_mlp(S, sb, tid, wid, l, w, count, list, scatp,
                nullptr, nullptr, x, eattr, p64, p32, is64, nE,
                blockIdx.x >> 1, gridDim.x >> 1, nullptr);
    }
    grid_barrier(2);

    // ---- phase 3: node MLP ----
    stage_weights(S, tid, Wn1, bn1, Wn2, bn2);
    __syncthreads();
    run_mlp(S, sb, tid, wid, l, 2, nN, nullptr, nullptr,
            g_flow_in, g_flow_out, x, eattr, p64, p32, is64, nE,
            blockIdx.x, gridDim.x, nodeout);
}

// ---------------- launch ----------------
extern "C" void kernel_launch(void* const* d_in, const int* in_sizes, int n_in,
                              void* d_out, int out_size) {
    const float* x     = (const float*)d_in[0];
    const void*  eidx  = d_in[1];
    const float* eattr = (const float*)d_in[2];
    const float* Wo1 = (const float*)d_in[3];
    const float* bo1 = (const float*)d_in[4];
    const float* Wo2 = (const float*)d_in[5];
    const float* bo2 = (const float*)d_in[6];
    const float* Wi1 = (const float*)d_in[7];
    const float* bi1 = (const float*)d_in[8];
    const float* Wi2 = (const float*)d_in[9];
    const float* bi2 = (const float*)d_in[10];
    const float* Wn1 = (const float*)d_in[11];
    const float* bn1 = (const float*)d_in[12];
    const float* Wn2 = (const float*)d_in[13];
    const float* bn2 = (const float*)d_in[14];

    int nN = in_sizes[0] / 64;
    int nE = in_sizes[2] / 64;

    cudaFuncSetAttribute(fused_kernel, cudaFuncAttributeMaxDynamicSharedMemorySize, SMEM_TOTAL);

    fused_kernel<<<GRID, 256, SMEM_TOTAL>>>(nN, nE, x, eidx, eattr,
                                            Wo1, bo1, Wo2, bo2,
                                            Wi1, bi1, Wi2, bi2,
                                            Wn1, bn1, Wn2, bn2,
                                            (float*)d_out);
}